// round 1
// baseline (speedup 1.0000x reference)
#include <cuda_runtime.h>

#define BTOT 4
#define NTOK 4096
#define CCH  128
#define TOKENS_ALL (BTOT * NTOK)

// scratch for projected q, k, v  (8 MB each, static device globals — allocation-free)
__device__ float g_q[TOKENS_ALL * CCH];
__device__ float g_k[TOKENS_ALL * CCH];
__device__ float g_v[TOKENS_ALL * CCH];

// ---------------------------------------------------------------------------
// Kernel 1: fused QKV projection.  q/k/v[n][co] = sum_ci x[n][ci]*W[ci][co]+b
// grid = TOKENS_ALL/128 blocks, 256 threads. Tile: 128 tokens x 128 outs,
// thread computes 8 tokens x 8 outs per matrix.
// ---------------------------------------------------------------------------
__global__ __launch_bounds__(256) void qkv_kernel(
    const float* __restrict__ x,
    const float* __restrict__ Wq, const float* __restrict__ bq,
    const float* __restrict__ Wk, const float* __restrict__ bk,
    const float* __restrict__ Wv, const float* __restrict__ bv)
{
    extern __shared__ float sm[];
    float* xs = sm;               // [128][132]  (pad 132 -> conflict-free reads)
    float* ws = sm + 128 * 132;   // [128][128]

    const int tid = threadIdx.x;
    const int tx = tid & 15, ty = tid >> 4;
    const int tok0 = blockIdx.x * 128;

    // load x tile (coalesced), pad-132 rows
    #pragma unroll
    for (int it = 0; it < 16; ++it) {
        int idx = it * 256 + tid;
        int t = idx >> 5, ch = idx & 31;
        float4 v = *(const float4*)(x + (size_t)(tok0 + t) * CCH + ch * 4);
        *(float4*)(xs + t * 132 + ch * 4) = v;
    }

    const float* Wmat[3] = {Wq, Wk, Wv};
    const float* bvec[3] = {bq, bk, bv};
    float* omat[3];
    omat[0] = g_q; omat[1] = g_k; omat[2] = g_v;

    for (int m = 0; m < 3; ++m) {
        __syncthreads();
        #pragma unroll
        for (int it = 0; it < 16; ++it) {
            int idx = it * 256 + tid;
            *(float4*)(ws + idx * 4) = *(const float4*)(Wmat[m] + idx * 4);
        }
        __syncthreads();

        float acc[8][8];
        #pragma unroll
        for (int i = 0; i < 8; ++i)
            #pragma unroll
            for (int j = 0; j < 8; ++j) acc[i][j] = 0.f;

        #pragma unroll 4
        for (int kk = 0; kk < 128; ++kk) {
            float xv[8];
            #pragma unroll
            for (int i = 0; i < 4; ++i) {
                xv[i]     = xs[(4 * ty + i) * 132 + kk];
                xv[4 + i] = xs[(64 + 4 * ty + i) * 132 + kk];
            }
            float4 w0 = *(float4*)(ws + kk * 128 + 4 * tx);
            float4 w1 = *(float4*)(ws + kk * 128 + 64 + 4 * tx);
            float wv[8] = {w0.x, w0.y, w0.z, w0.w, w1.x, w1.y, w1.z, w1.w};
            #pragma unroll
            for (int i = 0; i < 8; ++i)
                #pragma unroll
                for (int j = 0; j < 8; ++j)
                    acc[i][j] += xv[i] * wv[j];
        }

        float bb[8];
        #pragma unroll
        for (int j = 0; j < 4; ++j) {
            bb[j]     = bvec[m][4 * tx + j];
            bb[4 + j] = bvec[m][64 + 4 * tx + j];
        }
        float* o = omat[m];
        #pragma unroll
        for (int i = 0; i < 8; ++i) {
            int t = tok0 + ((i < 4) ? (4 * ty + i) : (64 + 4 * ty + (i - 4)));
            float4 s0 = {acc[i][0] + bb[0], acc[i][1] + bb[1],
                         acc[i][2] + bb[2], acc[i][3] + bb[3]};
            float4 s1 = {acc[i][4] + bb[4], acc[i][5] + bb[5],
                         acc[i][6] + bb[6], acc[i][7] + bb[7]};
            *(float4*)(o + (size_t)t * CCH + 4 * tx)      = s0;
            *(float4*)(o + (size_t)t * CCH + 64 + 4 * tx) = s1;
        }
    }
}

// ---------------------------------------------------------------------------
// Kernel 2: flash attention + residual.
// grid = (N/64, B), 256 threads/block. Block owns 64 query rows; streams
// 64-key tiles with online softmax. Thread: 4 rows x 4 S-cols; 4 rows x 8
// out-channels. q/k SMEM XOR-swizzled for conflict-free strided reads.
// ---------------------------------------------------------------------------
__global__ __launch_bounds__(256, 2) void attn_kernel(
    const float* __restrict__ x, float* __restrict__ out)
{
    extern __shared__ float sm[];
    float* qs = sm;                 // 64x128 swizzled (q pre-scaled by 1/sqrt(C))
    float* ks = sm + 64 * 128;      // 64x128 swizzled
    float* vs = sm + 2 * 64 * 128;  // 64x128 natural
    float* ps = sm + 3 * 64 * 128;  // 64x65  (pad 65)

    const int tid = threadIdx.x;
    const int tx = tid & 15, ty = tid >> 4;
    const int b  = blockIdx.y;
    const int q0 = blockIdx.x * 64;
    const size_t base = (size_t)b * NTOK * CCH;
    const float scale = 0.08838834764831845f;  // 1/sqrt(128)

    // load q tile, pre-scaled, swizzled: float4 slot ch -> ch ^ ((row>>2)&7)
    #pragma unroll
    for (int it = 0; it < 8; ++it) {
        int idx = it * 256 + tid;
        int r = idx >> 5, ch = idx & 31;
        float4 v = *(const float4*)(g_q + base + (size_t)(q0 + r) * CCH + ch * 4);
        v.x *= scale; v.y *= scale; v.z *= scale; v.w *= scale;
        *(float4*)(qs + r * 128 + 4 * (ch ^ ((r >> 2) & 7))) = v;
    }

    float acc[4][8];
    #pragma unroll
    for (int i = 0; i < 4; ++i)
        #pragma unroll
        for (int c = 0; c < 8; ++c) acc[i][c] = 0.f;
    float mrow[4], lrow[4];
    #pragma unroll
    for (int i = 0; i < 4; ++i) { mrow[i] = -1e30f; lrow[i] = 0.f; }

    for (int kt = 0; kt < NTOK / 64; ++kt) {
        __syncthreads();   // previous tile's ps/vs fully consumed
        const int k0 = kt * 64;
        #pragma unroll
        for (int it = 0; it < 8; ++it) {
            int idx = it * 256 + tid;
            int r = idx >> 5, ch = idx & 31;
            float4 kv = *(const float4*)(g_k + base + (size_t)(k0 + r) * CCH + ch * 4);
            *(float4*)(ks + r * 128 + 4 * (ch ^ ((r >> 2) & 7))) = kv;
            float4 vv = *(const float4*)(g_v + base + (size_t)(k0 + r) * CCH + ch * 4);
            *(float4*)(vs + r * 128 + ch * 4) = vv;
        }
        __syncthreads();

        // ---- S = q @ k^T (pre-scaled) ----
        float s[4][4];
        #pragma unroll
        for (int i = 0; i < 4; ++i)
            #pragma unroll
            for (int j = 0; j < 4; ++j) s[i][j] = 0.f;

        #pragma unroll 4
        for (int ch = 0; ch < 32; ++ch) {
            float4 qv[4], kv[4];
            #pragma unroll
            for (int i = 0; i < 4; ++i)
                qv[i] = *(float4*)(qs + (4 * ty + i) * 128 + 4 * (ch ^ (ty & 7)));
            #pragma unroll
            for (int j = 0; j < 4; ++j)
                kv[j] = *(float4*)(ks + (4 * tx + j) * 128 + 4 * (ch ^ (tx & 7)));
            #pragma unroll
            for (int i = 0; i < 4; ++i)
                #pragma unroll
                for (int j = 0; j < 4; ++j)
                    s[i][j] += qv[i].x * kv[j].x + qv[i].y * kv[j].y +
                               qv[i].z * kv[j].z + qv[i].w * kv[j].w;
        }

        // ---- online softmax (row reduce across 16 tx lanes via shfl) ----
        float mnew[4], alpha[4];
        #pragma unroll
        for (int i = 0; i < 4; ++i) {
            float mt = fmaxf(fmaxf(s[i][0], s[i][1]), fmaxf(s[i][2], s[i][3]));
            #pragma unroll
            for (int off = 8; off; off >>= 1)
                mt = fmaxf(mt, __shfl_xor_sync(0xffffffffu, mt, off));
            mnew[i]  = fmaxf(mrow[i], mt);
            alpha[i] = __expf(mrow[i] - mnew[i]);
            mrow[i]  = mnew[i];
        }
        #pragma unroll
        for (int i = 0; i < 4; ++i) {
            float r = 0.f;
            #pragma unroll
            for (int j = 0; j < 4; ++j) {
                float p = __expf(s[i][j] - mnew[i]);
                s[i][j] = p;
                r += p;
            }
            #pragma unroll
            for (int off = 8; off; off >>= 1)
                r += __shfl_xor_sync(0xffffffffu, r, off);
            lrow[i] = lrow[i] * alpha[i] + r;
            #pragma unroll
            for (int c = 0; c < 8; ++c) acc[i][c] *= alpha[i];
        }

        // stage P to smem (padded row 65)
        #pragma unroll
        for (int i = 0; i < 4; ++i)
            #pragma unroll
            for (int j = 0; j < 4; ++j)
                ps[(4 * ty + i) * 65 + 4 * tx + j] = s[i][j];
        __syncthreads();

        // ---- acc += P @ V ----
        #pragma unroll 8
        for (int kk = 0; kk < 64; ++kk) {
            float4 v0 = *(float4*)(vs + kk * 128 + 4 * tx);
            float4 v1 = *(float4*)(vs + kk * 128 + 64 + 4 * tx);
            #pragma unroll
            for (int i = 0; i < 4; ++i) {
                float p = ps[(4 * ty + i) * 65 + kk];
                acc[i][0] += p * v0.x; acc[i][1] += p * v0.y;
                acc[i][2] += p * v0.z; acc[i][3] += p * v0.w;
                acc[i][4] += p * v1.x; acc[i][5] += p * v1.y;
                acc[i][6] += p * v1.z; acc[i][7] += p * v1.w;
            }
        }
    }

    // ---- epilogue: out = x + acc / l ----
    #pragma unroll
    for (int i = 0; i < 4; ++i) {
        float inv = 1.0f / lrow[i];
        size_t row = base + (size_t)(q0 + 4 * ty + i) * CCH;
        float4 x0 = *(const float4*)(x + row + 4 * tx);
        float4 x1 = *(const float4*)(x + row + 64 + 4 * tx);
        float4 o0 = {x0.x + acc[i][0] * inv, x0.y + acc[i][1] * inv,
                     x0.z + acc[i][2] * inv, x0.w + acc[i][3] * inv};
        float4 o1 = {x1.x + acc[i][4] * inv, x1.y + acc[i][5] * inv,
                     x1.z + acc[i][6] * inv, x1.w + acc[i][7] * inv};
        *(float4*)(out + row + 4 * tx)      = o0;
        *(float4*)(out + row + 64 + 4 * tx) = o1;
    }
}

// ---------------------------------------------------------------------------
extern "C" void kernel_launch(void* const* d_in, const int* in_sizes, int n_in,
                              void* d_out, int out_size)
{
    const float* x  = (const float*)d_in[0];
    const float* Wq = (const float*)d_in[1];
    const float* bq = (const float*)d_in[2];
    const float* Wk = (const float*)d_in[3];
    const float* bk = (const float*)d_in[4];
    const float* Wv = (const float*)d_in[5];
    const float* bv = (const float*)d_in[6];
    float* out = (float*)d_out;

    const int qkv_smem  = (128 * 132 + 128 * 128) * 4;      // 133120 B
    const int attn_smem = (3 * 64 * 128 + 64 * 65) * 4;     // 114944 B
    cudaFuncSetAttribute(qkv_kernel,
                         cudaFuncAttributeMaxDynamicSharedMemorySize, qkv_smem);
    cudaFuncSetAttribute(attn_kernel,
                         cudaFuncAttributeMaxDynamicSharedMemorySize, attn_smem);

    qkv_kernel<<<TOKENS_ALL / 128, 256, qkv_smem>>>(x, Wq, bq, Wk, bk, Wv, bv);
    attn_kernel<<<dim3(NTOK / 64, BTOT), 256, attn_smem>>>(x, out);
}